// round 9
// baseline (speedup 1.0000x reference)
#include <cuda_runtime.h>
#include <cuda_bf16.h>
#include <math.h>
#include <float.h>
#include <stdint.h>

// Problem constants
#define B_    2
#define T_    2048
#define DM_   2048
#define HQ_   32
#define HKV_  8
#define HD_   64
#define LOG2_THETA 13.287712379549449

// bf16 hi/lo split buffers (no allocs -> __device__ globals)
__device__ __nv_bfloat16 g_xhi[(size_t)4096 * 2048];
__device__ __nv_bfloat16 g_xlo[(size_t)4096 * 2048];
__device__ __nv_bfloat16 g_Whi[(size_t)3072 * 2048];   // WQ|WK|WV rows
__device__ __nv_bfloat16 g_Wlo[(size_t)3072 * 2048];
__device__ __nv_bfloat16 g_WOhi[(size_t)2048 * 2048];
__device__ __nv_bfloat16 g_WOlo[(size_t)2048 * 2048];
__device__ __nv_bfloat16 g_Ohi[(size_t)4096 * 2048];   // attention out
__device__ __nv_bfloat16 g_Olo[(size_t)4096 * 2048];
__device__ __nv_bfloat16 g_Qhi[(size_t)B_ * HQ_  * T_ * HD_];  // rope'd, pre-scaled
__device__ __nv_bfloat16 g_Qlo[(size_t)B_ * HQ_  * T_ * HD_];
__device__ __nv_bfloat16 g_Khi[(size_t)B_ * HKV_ * T_ * HD_];  // rope'd
__device__ __nv_bfloat16 g_Klo[(size_t)B_ * HKV_ * T_ * HD_];
__device__ __nv_bfloat16 g_Vhi[(size_t)B_ * HKV_ * T_ * HD_];
__device__ __nv_bfloat16 g_Vlo[(size_t)B_ * HKV_ * T_ * HD_];

// ============================================================================
// PTX helpers (legacy tensor path + cp.async: plain PTX, valid on compute_103)
// ============================================================================
__device__ __forceinline__ uint32_t smem_u32(const void* p) {
    uint32_t a;
    asm("{ .reg .u64 t; cvta.to.shared.u64 t, %1; cvt.u32.u64 %0, t; }"
        : "=r"(a) : "l"(p));
    return a;
}
__device__ __forceinline__ void ldsm_x4(uint32_t& r0, uint32_t& r1,
                                        uint32_t& r2, uint32_t& r3, uint32_t a) {
    asm volatile("ldmatrix.sync.aligned.m8n8.x4.shared.b16 {%0,%1,%2,%3}, [%4];"
                 : "=r"(r0), "=r"(r1), "=r"(r2), "=r"(r3) : "r"(a));
}
__device__ __forceinline__ void ldsm_x4_t(uint32_t& r0, uint32_t& r1,
                                          uint32_t& r2, uint32_t& r3, uint32_t a) {
    asm volatile("ldmatrix.sync.aligned.m8n8.x4.trans.shared.b16 {%0,%1,%2,%3}, [%4];"
                 : "=r"(r0), "=r"(r1), "=r"(r2), "=r"(r3) : "r"(a));
}
__device__ __forceinline__ void mma16816(float* d, const uint32_t* a, const uint32_t* b) {
    asm volatile(
        "mma.sync.aligned.m16n8k16.row.col.f32.bf16.bf16.f32 "
        "{%0,%1,%2,%3}, {%4,%5,%6,%7}, {%8,%9}, {%0,%1,%2,%3};"
        : "+f"(d[0]), "+f"(d[1]), "+f"(d[2]), "+f"(d[3])
        : "r"(a[0]), "r"(a[1]), "r"(a[2]), "r"(a[3]), "r"(b[0]), "r"(b[1]));
}
__device__ __forceinline__ void cp16(uint32_t dst, const void* src) {
    asm volatile("cp.async.cg.shared.global [%0], [%1], 16;" :: "r"(dst), "l"(src));
}
#define CP_COMMIT() asm volatile("cp.async.commit_group;" ::: "memory")
#define CP_WAIT0()  asm volatile("cp.async.wait_group 0;" ::: "memory")

__device__ __forceinline__ void split1(float v, __nv_bfloat16& h, __nv_bfloat16& l) {
    h = __float2bfloat16_rn(v);
    l = __float2bfloat16_rn(v - __bfloat162float(h));
}
__device__ __forceinline__ uint32_t pack_hl(float a, float b, uint32_t& lo) {
    __nv_bfloat16 ha, hb, la, lb;
    split1(a, ha, la);
    split1(b, hb, lb);
    lo = (uint32_t)__bfloat16_as_ushort(la) | ((uint32_t)__bfloat16_as_ushort(lb) << 16);
    return (uint32_t)__bfloat16_as_ushort(ha) | ((uint32_t)__bfloat16_as_ushort(hb) << 16);
}

// ============================================================================
// Kernel 0: fp32 -> (hi, lo) bf16 conversion for x, WQ|WK|WV, WO.
// ============================================================================
#define NE_X   8388608ull
#define NE_WQ  4194304ull
#define NE_WKV 1048576ull
#define CVT_TOTAL_F4 4718592

__global__ __launch_bounds__(256)
void cvt_kernel(const float* __restrict__ x,  const float* __restrict__ WQ,
                const float* __restrict__ WK, const float* __restrict__ WV,
                const float* __restrict__ WO)
{
    const size_t e = ((size_t)blockIdx.x * 256 + threadIdx.x) * 4;
    const float* src; __nv_bfloat16 *dh, *dl; size_t off;
    if (e < NE_X)                          { src = x;  dh = g_xhi;            dl = g_xlo;            off = e; }
    else if (e < NE_X + NE_WQ)             { src = WQ; dh = g_Whi;            dl = g_Wlo;            off = e - NE_X; }
    else if (e < NE_X + NE_WQ + NE_WKV)    { src = WK; dh = g_Whi + 4194304;  dl = g_Wlo + 4194304;  off = e - NE_X - NE_WQ; }
    else if (e < NE_X + NE_WQ + 2*NE_WKV)  { src = WV; dh = g_Whi + 5242880;  dl = g_Wlo + 5242880;  off = e - NE_X - NE_WQ - NE_WKV; }
    else                                   { src = WO; dh = g_WOhi;           dl = g_WOlo;           off = e - NE_X - NE_WQ - 2*NE_WKV; }
    float4 v = *(const float4*)(src + off);
    uint2 uh, ul;
    uh.x = pack_hl(v.x, v.y, ul.x);
    uh.y = pack_hl(v.z, v.w, ul.y);
    *(uint2*)(dh + off) = uh;
    *(uint2*)(dl + off) = ul;
}

// ============================================================================
// mma.sync split-fp32 GEMM, cp.async double-buffered.
// D[128x128] = A * B^T, K=2048, BK=32. 256 thr = 8 warps, warp tile 32x64.
// Smem layout (bf16 elems): A[buf][hl] regions of 5120 (=128*SPAD), then B.
// MODE 0: QKV proj -> RoPE -> hi/lo bf16 Q/K/V (Q pre-scaled by 0.125).
// MODE 1: out proj -> fp32 to outp.
// ============================================================================
#define SPAD 40
#define GREG_B 10240u                       // bytes per (buf,hl) region
#define GEMM_SMEM_BYTES (8 * GREG_B)        // A: 4 regions, B: 4 regions

template <int MODE>
__global__ __launch_bounds__(256)
void gemm_mma_kernel(const int* __restrict__ pos, float* __restrict__ outp)
{
    extern __shared__ __align__(16) __nv_bfloat16 smg[];
    const uint32_t smBase = smem_u32(smg);

    const int j0 = blockIdx.x * 128;
    const int m0 = blockIdx.y * 128;
    const int tid = threadIdx.x;
    const int wid = tid >> 5, lane = tid & 31;

    const __nv_bfloat16* Ahi = (MODE == 0) ? g_xhi : g_Ohi;
    const __nv_bfloat16* Alo = (MODE == 0) ? g_xlo : g_Olo;
    const __nv_bfloat16* Bhi = ((MODE == 0) ? g_Whi : g_WOhi) + (size_t)j0 * DM_;
    const __nv_bfloat16* Blo = ((MODE == 0) ? g_Wlo : g_WOlo) + (size_t)j0 * DM_;

    const int lrow = tid >> 1;
    const int lcol = (tid & 1) * 16;
    const size_t aoff = (size_t)(m0 + lrow) * DM_ + lcol;
    const size_t boff = (size_t)lrow * DM_ + lcol;
    const uint32_t sby = (uint32_t)(lrow * SPAD + lcol) * 2u;  // smem byte off in region

    const int wm = (wid & 3) * 32;
    const int wn = (wid >> 2) * 64;

    float acc[2][8][4];
#pragma unroll
    for (int mt = 0; mt < 2; mt++)
#pragma unroll
        for (int nt = 0; nt < 8; nt++)
#pragma unroll
            for (int q = 0; q < 4; q++) acc[mt][nt][q] = 0.f;

    // Issue async load of chunk kc into buffer buf
    auto issue_load = [&](int kc, int buf) {
        const size_t nk = (size_t)kc * 32;
        const uint32_t ab = smBase + (uint32_t)buf * (2 * GREG_B);
        const uint32_t bb = smBase + 4 * GREG_B + (uint32_t)buf * (2 * GREG_B);
        cp16(ab + sby,               Ahi + aoff + nk);
        cp16(ab + sby + 16,          Ahi + aoff + nk + 8);
        cp16(ab + GREG_B + sby,      Alo + aoff + nk);
        cp16(ab + GREG_B + sby + 16, Alo + aoff + nk + 8);
        cp16(bb + sby,               Bhi + boff + nk);
        cp16(bb + sby + 16,          Bhi + boff + nk + 8);
        cp16(bb + GREG_B + sby,      Blo + boff + nk);
        cp16(bb + GREG_B + sby + 16, Blo + boff + nk + 8);
        CP_COMMIT();
    };

    issue_load(0, 0);

    for (int kc = 0; kc < DM_ / 32; kc++) {
        CP_WAIT0();
        __syncthreads();
        if (kc + 1 < DM_ / 32) issue_load(kc + 1, (kc + 1) & 1);

        const uint32_t aB = smBase + (uint32_t)(kc & 1) * (2 * GREG_B);
        const uint32_t bB = smBase + 4 * GREG_B + (uint32_t)(kc & 1) * (2 * GREG_B);

#pragma unroll
        for (int ks = 0; ks < 2; ks++) {
            uint32_t bh[8][2], bl[8][2];
            const int brow = wn + ((lane >> 4) & 1) * 8 + (lane & 7);
            const int bcol = ks * 16 + ((lane >> 3) & 1) * 8;
#pragma unroll
            for (int p = 0; p < 4; p++) {
                const uint32_t off = (uint32_t)((brow + p * 16) * SPAD + bcol) * 2u;
                ldsm_x4(bh[2*p][0], bh[2*p][1], bh[2*p+1][0], bh[2*p+1][1], bB + off);
                ldsm_x4(bl[2*p][0], bl[2*p][1], bl[2*p+1][0], bl[2*p+1][1],
                        bB + GREG_B + off);
            }
            const int arow = wm + (lane & 15);
            const int acol = ks * 16 + (lane >> 4) * 8;
#pragma unroll
            for (int mt = 0; mt < 2; mt++) {
                uint32_t ah[4], al[4];
                const uint32_t off = (uint32_t)((arow + mt * 16) * SPAD + acol) * 2u;
                ldsm_x4(ah[0], ah[1], ah[2], ah[3], aB + off);
                ldsm_x4(al[0], al[1], al[2], al[3], aB + GREG_B + off);
#pragma unroll
                for (int nt = 0; nt < 8; nt++) mma16816(acc[mt][nt], ah, bh[nt]);
#pragma unroll
                for (int nt = 0; nt < 8; nt++) mma16816(acc[mt][nt], ah, bl[nt]);
#pragma unroll
                for (int nt = 0; nt < 8; nt++) mma16816(acc[mt][nt], al, bh[nt]);
            }
        }
    }

    // ---- Epilogue ----
    const int cpair = 2 * (lane & 3);
    if (MODE == 1) {
#pragma unroll
        for (int mt = 0; mt < 2; mt++)
#pragma unroll
            for (int half = 0; half < 2; half++) {
                const int m = m0 + wm + mt * 16 + (lane >> 2) + half * 8;
                float* dst = outp + (size_t)m * DM_ + j0 + wn + cpair;
#pragma unroll
                for (int nt = 0; nt < 8; nt++)
                    *(float2*)(dst + nt * 8) =
                        make_float2(acc[mt][nt][2 * half], acc[mt][nt][2 * half + 1]);
            }
    } else {
        const int jb = j0 + wn;
        const bool isV = (jb >= 2560);
        const bool isQ = (jb < 2048);
        const int head = isQ ? (jb >> 6) : (jb < 2560 ? ((jb - 2048) >> 6) : ((jb - 2560) >> 6));
        double invf[8];
        if (!isV) {
#pragma unroll
            for (int nt = 0; nt < 8; nt++) {
                const int pi = nt * 4 + (lane & 3);
                invf[nt] = exp2(-(2.0 * pi) * (LOG2_THETA / 64.0));
            }
        }
#pragma unroll
        for (int mt = 0; mt < 2; mt++)
#pragma unroll
            for (int half = 0; half < 2; half++) {
                const int m = m0 + wm + mt * 16 + (lane >> 2) + half * 8;
                const int bb = m >> 11;
                const int t  = m & (T_ - 1);
                if (isV) {
                    const size_t doff =
                        (((size_t)bb * HKV_ + head) * T_ + t) * HD_ + cpair;
#pragma unroll
                    for (int nt = 0; nt < 8; nt++) {
                        uint32_t lo;
                        uint32_t hi = pack_hl(acc[mt][nt][2 * half],
                                              acc[mt][nt][2 * half + 1], lo);
                        *(uint32_t*)(g_Vhi + doff + nt * 8) = hi;
                        *(uint32_t*)(g_Vlo + doff + nt * 8) = lo;
                    }
                } else {
                    const int p = pos[t];
                    const float qs = isQ ? 0.125f : 1.0f;
                    const size_t doff = isQ
                        ? (((size_t)bb * HQ_  + head) * T_ + t) * HD_ + cpair
                        : (((size_t)bb * HKV_ + head) * T_ + t) * HD_ + cpair;
                    __nv_bfloat16* dsth = isQ ? g_Qhi : g_Khi;
                    __nv_bfloat16* dstl = isQ ? g_Qlo : g_Klo;
#pragma unroll
                    for (int nt = 0; nt < 8; nt++) {
                        double sn, cs;
                        sincos((double)p * invf[nt], &sn, &cs);
                        const float fc = (float)cs, fs = (float)sn;
                        const float fe = acc[mt][nt][2 * half];
                        const float fo = acc[mt][nt][2 * half + 1];
                        uint32_t lo;
                        uint32_t hi = pack_hl((fe * fc - fo * fs) * qs,
                                              (fe * fs + fo * fc) * qs, lo);
                        *(uint32_t*)(dsth + doff + nt * 8) = hi;
                        *(uint32_t*)(dstl + doff + nt * 8) = lo;
                    }
                }
            }
    }
}

// ============================================================================
// Causal GQA flash attention on tensor cores, cp.async double-buffered K/V.
// 128 threads = 4 warps; BM=128, BN=64, HD=64. Split-fp32 (3 passes each GEMM).
// Smem (bf16 elems): Qh/Ql 9216 each; K/V buf{0,1}: Kh,Kl,Vh,Vl 4608 each.
// 108 KB dyn smem -> 2 CTAs/SM.
// ============================================================================
#define APAD 72
#define AQ_ELEMS (128 * APAD)               // 9216
#define AKV_ELEMS (64 * APAD)               // 4608
#define AKV_BUF_BYTES (4 * AKV_ELEMS * 2)   // 36864
#define ATTN_SMEM_BYTES (2 * AQ_ELEMS * 2 + 2 * AKV_BUF_BYTES)

__global__ __launch_bounds__(128, 2)
void attn_mma_kernel()
{
    extern __shared__ __align__(16) __nv_bfloat16 smb[];
    const uint32_t smBase = smem_u32(smb);
    const uint32_t QhB = smBase;
    const uint32_t QlB = smBase + AQ_ELEMS * 2;
    const uint32_t KV0 = smBase + 2 * AQ_ELEMS * 2;     // buf0 Kh

    const int qt = (int)gridDim.x - 1 - (int)blockIdx.x;
    const int hq = blockIdx.y;
    const int bb = blockIdx.z;
    const int hk = hq >> 2;

    const int tid = threadIdx.x;
    const int wid = tid >> 5, lane = tid & 31;
    const int wm = wid * 32;
    const int gID = lane >> 2, tig = lane & 3;

    // Load Q tile (hi/lo): one 64-elem row per thread (plain loads, once)
    {
        const size_t qoff = (((size_t)bb * HQ_ + hq) * T_ + (size_t)qt * 128 + tid) * HD_;
        __nv_bfloat16* Qh = smb;
        __nv_bfloat16* Ql = smb + AQ_ELEMS;
#pragma unroll
        for (int v = 0; v < 8; v++) {
            *(uint4*)&Qh[tid * APAD + v * 8] = *(const uint4*)(g_Qhi + qoff + v * 8);
            *(uint4*)&Ql[tid * APAD + v * 8] = *(const uint4*)(g_Qlo + qoff + v * 8);
        }
    }

    float O[2][8][4];
#pragma unroll
    for (int mt = 0; mt < 2; mt++)
#pragma unroll
        for (int nt = 0; nt < 8; nt++)
#pragma unroll
            for (int q = 0; q < 4; q++) O[mt][nt][q] = 0.f;
    float m_st[2][2], l_st[2][2];
#pragma unroll
    for (int mt = 0; mt < 2; mt++)
#pragma unroll
        for (int h2 = 0; h2 < 2; h2++) { m_st[mt][h2] = -FLT_MAX; l_st[mt][h2] = 0.f; }

    const size_t kvbase = ((size_t)bb * HKV_ + hk) * T_ * HD_;
    const int lrow = tid >> 1;
    const int lhalf = (tid & 1) * 32;
    const uint32_t sby = (uint32_t)(lrow * APAD + lhalf) * 2u;
    const int ktmax = 2 * qt + 1;

    auto issue_kv = [&](int kt, int buf) {
        const size_t goff = kvbase + ((size_t)kt * 64 + lrow) * HD_ + lhalf;
        const uint32_t kb = KV0 + (uint32_t)buf * AKV_BUF_BYTES;
#pragma unroll
        for (int v = 0; v < 4; v++) {
            cp16(kb + sby + v * 16,                     g_Khi + goff + v * 8);
            cp16(kb + 1 * AKV_ELEMS * 2 + sby + v * 16, g_Klo + goff + v * 8);
            cp16(kb + 2 * AKV_ELEMS * 2 + sby + v * 16, g_Vhi + goff + v * 8);
            cp16(kb + 3 * AKV_ELEMS * 2 + sby + v * 16, g_Vlo + goff + v * 8);
        }
        CP_COMMIT();
    };

    issue_kv(0, 0);

    for (int kt = 0; kt <= ktmax; kt++) {
        CP_WAIT0();
        __syncthreads();
        if (kt < ktmax) issue_kv(kt + 1, (kt + 1) & 1);

        const uint32_t kb  = KV0 + (uint32_t)(kt & 1) * AKV_BUF_BYTES;
        const uint32_t KhA = kb;
        const uint32_t KlA = kb + 1 * AKV_ELEMS * 2;
        const uint32_t VhA = kb + 2 * AKV_ELEMS * 2;
        const uint32_t VlA = kb + 3 * AKV_ELEMS * 2;

        // ---- S = Q K^T (3 passes) ----
        float S[2][8][4];
#pragma unroll
        for (int mt = 0; mt < 2; mt++)
#pragma unroll
            for (int nt = 0; nt < 8; nt++)
#pragma unroll
                for (int q = 0; q < 4; q++) S[mt][nt][q] = 0.f;

#pragma unroll
        for (int ks = 0; ks < 4; ks++) {
            uint32_t bh[8][2], bl[8][2];
            const int brow = ((lane >> 4) & 1) * 8 + (lane & 7);
            const int bcol = ks * 16 + ((lane >> 3) & 1) * 8;
#pragma unroll
            for (int p = 0; p < 4; p++) {
                const uint32_t off = (uint32_t)((brow + p * 16) * APAD + bcol) * 2u;
                ldsm_x4(bh[2*p][0], bh[2*p][1], bh[2*p+1][0], bh[2*p+1][1], KhA + off);
                ldsm_x4(bl[2*p][0], bl[2*p][1], bl[2*p+1][0], bl[2*p+1][1], KlA + off);
            }
            const int arow = wm + (lane & 15);
            const int acol = ks * 16 + (lane >> 4) * 8;
#pragma unroll
            for (int mt = 0; mt < 2; mt++) {
                uint32_t ah[4], al[4];
                const uint32_t off = (uint32_t)((arow + mt * 16) * APAD + acol) * 2u;
                ldsm_x4(ah[0], ah[1], ah[2], ah[3], QhB + off);
                ldsm_x4(al[0], al[1], al[2], al[3], QlB + off);
#pragma unroll
                for (int nt = 0; nt < 8; nt++) mma16816(S[mt][nt], ah, bh[nt]);
#pragma unroll
                for (int nt = 0; nt < 8; nt++) mma16816(S[mt][nt], ah, bl[nt]);
#pragma unroll
                for (int nt = 0; nt < 8; nt++) mma16816(S[mt][nt], al, bh[nt]);
            }
        }

        // ---- Causal mask (diagonal tiles only) ----
        if (kt >= 2 * qt) {
            const int rg = qt * 128 + wm + gID;
            const int cg = kt * 64 + 2 * tig;
#pragma unroll
            for (int mt = 0; mt < 2; mt++)
#pragma unroll
                for (int nt = 0; nt < 8; nt++)
#pragma unroll
                    for (int h2 = 0; h2 < 2; h2++)
#pragma unroll
                        for (int e = 0; e < 2; e++)
                            if (cg + nt * 8 + e > rg + mt * 16 + h2 * 8)
                                S[mt][nt][2 * h2 + e] = -FLT_MAX;
        }

        // ---- Online softmax (quad rows; shfl_xor 1,2) ----
#pragma unroll
        for (int mt = 0; mt < 2; mt++)
#pragma unroll
            for (int h2 = 0; h2 < 2; h2++) {
                float mx = -FLT_MAX;
#pragma unroll
                for (int nt = 0; nt < 8; nt++)
                    mx = fmaxf(mx, fmaxf(S[mt][nt][2 * h2], S[mt][nt][2 * h2 + 1]));
                mx = fmaxf(mx, __shfl_xor_sync(0xffffffffu, mx, 1));
                mx = fmaxf(mx, __shfl_xor_sync(0xffffffffu, mx, 2));
                const float nm = fmaxf(m_st[mt][h2], mx);
                float sum = 0.f;
#pragma unroll
                for (int nt = 0; nt < 8; nt++) {
                    S[mt][nt][2 * h2]     = __expf(S[mt][nt][2 * h2]     - nm);
                    S[mt][nt][2 * h2 + 1] = __expf(S[mt][nt][2 * h2 + 1] - nm);
                    sum += S[mt][nt][2 * h2] + S[mt][nt][2 * h2 + 1];
                }
                sum += __shfl_xor_sync(0xffffffffu, sum, 1);
                sum += __shfl_xor_sync(0xffffffffu, sum, 2);
                const float corr = __expf(m_st[mt][h2] - nm);
                m_st[mt][h2] = nm;
                l_st[mt][h2] = l_st[mt][h2] * corr + sum;
#pragma unroll
                for (int nt = 0; nt < 8; nt++) {
                    O[mt][nt][2 * h2]     *= corr;
                    O[mt][nt][2 * h2 + 1] *= corr;
                }
            }

        // ---- O += P V (3 passes; P packed register-locally) ----
#pragma unroll
        for (int ks = 0; ks < 4; ks++) {
            uint32_t vh[8][2], vl[8][2];
            const int vrow = ks * 16 + (lane & 15);
#pragma unroll
            for (int p = 0; p < 4; p++) {
                const uint32_t off =
                    (uint32_t)(vrow * APAD + p * 16 + (lane >> 4) * 8) * 2u;
                ldsm_x4_t(vh[2*p][0], vh[2*p][1], vh[2*p+1][0], vh[2*p+1][1], VhA + off);
                ldsm_x4_t(vl[2*p][0], vl[2*p][1], vl[2*p+1][0], vl[2*p+1][1], VlA + off);
            }
#pragma unroll
            for (int mt = 0; mt < 2; mt++) {
                uint32_t ah[4], al[4];
                ah[0] = pack_hl(S[mt][2*ks][0],   S[mt][2*ks][1],   al[0]);
                ah[1] = pack_hl(S[mt][2*ks][2],   S[mt][2*ks][3],   al[1]);
                ah[2] = pack_hl(S[mt][2*ks+1][0], S[mt][2*ks+1][1], al[2]);
                ah[3] = pack_hl(S[mt][2*ks+1][2], S[mt][2*ks+1][3], al[3]);
#pragma unroll
                for (int nt = 0; nt < 8; nt++) mma16816(O[mt][nt], ah, vh[nt]);
#pragma unroll
                for (int nt = 0; nt < 8; nt++) mma16816(O[mt][nt], ah, vl[nt]);
#pragma unroll
                for (int nt = 0; nt < 8; nt++) mma16816(O[mt][nt], al, vh[nt]);
            }
        }
    }

    // ---- Finalize: /l, split hi/lo, store for out-projection ----
#pragma unroll
    for (int mt = 0; mt < 2; mt++)
#pragma unroll
        for (int h2 = 0; h2 < 2; h2++) {
            const float inv = 1.0f / l_st[mt][h2];
            const int rg = qt * 128 + wm + mt * 16 + gID + h2 * 8;
            const size_t off = ((size_t)bb * T_ + rg) * DM_ + hq * HD_ + 2 * tig;
#pragma unroll
            for (int nt = 0; nt < 8; nt++) {
                uint32_t lo;
                uint32_t hi = pack_hl(O[mt][nt][2 * h2] * inv,
                                      O[mt][nt][2 * h2 + 1] * inv, lo);
                *(uint32_t*)(g_Ohi + off + nt * 8) = hi;
                *(uint32_t*)(g_Olo + off + nt * 8) = lo;
            }
        }
}

// ============================================================================
extern "C" void kernel_launch(void* const* d_in, const int* in_sizes, int n_in,
                              void* d_out, int out_size)
{
    const float* x   = (const float*)d_in[0];
    const int*   pos = (const int*)  d_in[1];
    const float* WQ  = (const float*)d_in[2];
    const float* WK  = (const float*)d_in[3];
    const float* WV  = (const float*)d_in[4];
    const float* WO  = (const float*)d_in[5];
    float* out = (float*)d_out;

    cudaFuncSetAttribute(gemm_mma_kernel<0>, cudaFuncAttributeMaxDynamicSharedMemorySize,
                         GEMM_SMEM_BYTES);
    cudaFuncSetAttribute(gemm_mma_kernel<1>, cudaFuncAttributeMaxDynamicSharedMemorySize,
                         GEMM_SMEM_BYTES);
    cudaFuncSetAttribute(attn_mma_kernel, cudaFuncAttributeMaxDynamicSharedMemorySize,
                         ATTN_SMEM_BYTES);

    // 0) hi/lo bf16 conversion of x and all weights
    cvt_kernel<<<CVT_TOTAL_F4 / 256, 256>>>(x, WQ, WK, WV, WO);

    // 1) QKV projection + RoPE (tensor cores) -> bf16 hi/lo Q/K/V
    gemm_mma_kernel<0><<<dim3(24, (B_ * T_) / 128), 256, GEMM_SMEM_BYTES>>>(pos, nullptr);

    // 2) Flash attention (tensor cores, split-fp32) -> bf16 hi/lo O
    attn_mma_kernel<<<dim3(T_ / 128, HQ_, B_), 128, ATTN_SMEM_BYTES>>>();

    // 3) Output projection (tensor cores) -> fp32 out
    gemm_mma_kernel<1><<<dim3(16, (B_ * T_) / 128), 256, GEMM_SMEM_BYTES>>>(pos, out);
}

// round 10
// speedup vs baseline: 1.6668x; 1.6668x over previous
#include <cuda_runtime.h>
#include <cuda_bf16.h>
#include <math.h>
#include <float.h>
#include <stdint.h>

// Problem constants
#define B_    2
#define T_    2048
#define DM_   2048
#define HQ_   32
#define HKV_  8
#define HD_   64
#define LOG2_THETA 13.287712379549449

// bf16 hi/lo split buffers (no allocs -> __device__ globals)
__device__ __nv_bfloat16 g_xhi[(size_t)4096 * 2048];
__device__ __nv_bfloat16 g_xlo[(size_t)4096 * 2048];
__device__ __nv_bfloat16 g_Whi[(size_t)3072 * 2048];   // WQ|WK|WV rows
__device__ __nv_bfloat16 g_Wlo[(size_t)3072 * 2048];
__device__ __nv_bfloat16 g_WOhi[(size_t)2048 * 2048];
__device__ __nv_bfloat16 g_WOlo[(size_t)2048 * 2048];
__device__ __nv_bfloat16 g_Ohi[(size_t)4096 * 2048];   // attention out
__device__ __nv_bfloat16 g_Olo[(size_t)4096 * 2048];
__device__ __nv_bfloat16 g_Qhi[(size_t)B_ * HQ_  * T_ * HD_];  // rope'd, pre-scaled
__device__ __nv_bfloat16 g_Qlo[(size_t)B_ * HQ_  * T_ * HD_];
__device__ __nv_bfloat16 g_Khi[(size_t)B_ * HKV_ * T_ * HD_];  // rope'd
__device__ __nv_bfloat16 g_Klo[(size_t)B_ * HKV_ * T_ * HD_];
__device__ __nv_bfloat16 g_Vhi[(size_t)B_ * HKV_ * T_ * HD_];
__device__ __nv_bfloat16 g_Vlo[(size_t)B_ * HKV_ * T_ * HD_];

// ============================================================================
// PTX helpers (legacy tensor path: plain PTX, valid on compute_103)
// ============================================================================
__device__ __forceinline__ uint32_t smem_u32(const void* p) {
    uint32_t a;
    asm("{ .reg .u64 t; cvta.to.shared.u64 t, %1; cvt.u32.u64 %0, t; }"
        : "=r"(a) : "l"(p));
    return a;
}
__device__ __forceinline__ void ldsm_x4(uint32_t& r0, uint32_t& r1,
                                        uint32_t& r2, uint32_t& r3, uint32_t a) {
    asm volatile("ldmatrix.sync.aligned.m8n8.x4.shared.b16 {%0,%1,%2,%3}, [%4];"
                 : "=r"(r0), "=r"(r1), "=r"(r2), "=r"(r3) : "r"(a));
}
__device__ __forceinline__ void ldsm_x4_t(uint32_t& r0, uint32_t& r1,
                                          uint32_t& r2, uint32_t& r3, uint32_t a) {
    asm volatile("ldmatrix.sync.aligned.m8n8.x4.trans.shared.b16 {%0,%1,%2,%3}, [%4];"
                 : "=r"(r0), "=r"(r1), "=r"(r2), "=r"(r3) : "r"(a));
}
__device__ __forceinline__ void mma16816(float* d, const uint32_t* a, const uint32_t* b) {
    asm volatile(
        "mma.sync.aligned.m16n8k16.row.col.f32.bf16.bf16.f32 "
        "{%0,%1,%2,%3}, {%4,%5,%6,%7}, {%8,%9}, {%0,%1,%2,%3};"
        : "+f"(d[0]), "+f"(d[1]), "+f"(d[2]), "+f"(d[3])
        : "r"(a[0]), "r"(a[1]), "r"(a[2]), "r"(a[3]), "r"(b[0]), "r"(b[1]));
}
__device__ __forceinline__ void split1(float v, __nv_bfloat16& h, __nv_bfloat16& l) {
    h = __float2bfloat16_rn(v);
    l = __float2bfloat16_rn(v - __bfloat162float(h));
}
__device__ __forceinline__ uint32_t pack_hl(float a, float b, uint32_t& lo) {
    __nv_bfloat16 ha, hb, la, lb;
    split1(a, ha, la);
    split1(b, hb, lb);
    lo = (uint32_t)__bfloat16_as_ushort(la) | ((uint32_t)__bfloat16_as_ushort(lb) << 16);
    return (uint32_t)__bfloat16_as_ushort(ha) | ((uint32_t)__bfloat16_as_ushort(hb) << 16);
}

// ============================================================================
// Kernel 0: fp32 -> (hi, lo) bf16 conversion for x, WQ|WK|WV, WO.
// ============================================================================
#define NE_X   8388608ull
#define NE_WQ  4194304ull
#define NE_WKV 1048576ull
#define CVT_TOTAL_F4 4718592

__global__ __launch_bounds__(256)
void cvt_kernel(const float* __restrict__ x,  const float* __restrict__ WQ,
                const float* __restrict__ WK, const float* __restrict__ WV,
                const float* __restrict__ WO)
{
    const size_t e = ((size_t)blockIdx.x * 256 + threadIdx.x) * 4;
    const float* src; __nv_bfloat16 *dh, *dl; size_t off;
    if (e < NE_X)                          { src = x;  dh = g_xhi;            dl = g_xlo;            off = e; }
    else if (e < NE_X + NE_WQ)             { src = WQ; dh = g_Whi;            dl = g_Wlo;            off = e - NE_X; }
    else if (e < NE_X + NE_WQ + NE_WKV)    { src = WK; dh = g_Whi + 4194304;  dl = g_Wlo + 4194304;  off = e - NE_X - NE_WQ; }
    else if (e < NE_X + NE_WQ + 2*NE_WKV)  { src = WV; dh = g_Whi + 5242880;  dl = g_Wlo + 5242880;  off = e - NE_X - NE_WQ - NE_WKV; }
    else                                   { src = WO; dh = g_WOhi;           dl = g_WOlo;           off = e - NE_X - NE_WQ - 2*NE_WKV; }
    float4 v = *(const float4*)(src + off);
    uint2 uh, ul;
    uh.x = pack_hl(v.x, v.y, ul.x);
    uh.y = pack_hl(v.z, v.w, ul.y);
    *(uint2*)(dh + off) = uh;
    *(uint2*)(dl + off) = ul;
}

// ============================================================================
// mma.sync split-fp32 GEMM:  D[128x128] = A * B^T, K=2048, BK=32.
// 256 thr = 8 warps (4x2), warp tile 32x64. Double-buffered smem, ONE barrier
// per chunk (LDG->STS straight into the other buffer). 128-reg cap -> 2 CTA/SM.
// MODE 0: QKV proj -> RoPE -> hi/lo bf16 Q/K/V (Q pre-scaled by 0.125).
// MODE 1: out proj -> fp32 to outp.
// ============================================================================
#define SPAD 40
#define GREG_ELEMS 5120                      // 128*SPAD bf16 per region
#define GREG_B 10240u                        // bytes per region
#define GEMM_SMEM_BYTES (8 * GREG_B)         // 2 bufs x {Ahi,Alo,Bhi,Blo}

template <int MODE>
__global__ __launch_bounds__(256, 2)
void gemm_mma_kernel(const int* __restrict__ pos, float* __restrict__ outp)
{
    extern __shared__ __align__(16) __nv_bfloat16 smg[];
    const uint32_t smBase = smem_u32(smg);

    const int j0 = blockIdx.x * 128;
    const int m0 = blockIdx.y * 128;
    const int tid = threadIdx.x;
    const int wid = tid >> 5, lane = tid & 31;

    const __nv_bfloat16* Ahi = (MODE == 0) ? g_xhi : g_Ohi;
    const __nv_bfloat16* Alo = (MODE == 0) ? g_xlo : g_Olo;
    const __nv_bfloat16* Bhi = ((MODE == 0) ? g_Whi : g_WOhi) + (size_t)j0 * DM_;
    const __nv_bfloat16* Blo = ((MODE == 0) ? g_Wlo : g_WOlo) + (size_t)j0 * DM_;

    const int lrow = tid >> 1;
    const int lcol = (tid & 1) * 16;
    const size_t aoff = (size_t)(m0 + lrow) * DM_ + lcol;
    const size_t boff = (size_t)lrow * DM_ + lcol;
    const int sidx = lrow * SPAD + lcol;

    const int wm = (wid & 3) * 32;
    const int wn = (wid >> 2) * 64;

    float acc[2][8][4];
#pragma unroll
    for (int mt = 0; mt < 2; mt++)
#pragma unroll
        for (int nt = 0; nt < 8; nt++)
#pragma unroll
            for (int q = 0; q < 4; q++) acc[mt][nt][q] = 0.f;

    // LDG -> STS chunk kc into buffer buf
    auto load_chunk = [&](int kc, int buf) {
        const size_t nk = (size_t)kc * 32;
        __nv_bfloat16* p = smg + (size_t)buf * (4 * GREG_ELEMS);
        *(uint4*)&p[sidx]                      = *(const uint4*)(Ahi + aoff + nk);
        *(uint4*)&p[sidx + 8]                  = *(const uint4*)(Ahi + aoff + nk + 8);
        *(uint4*)&p[GREG_ELEMS + sidx]         = *(const uint4*)(Alo + aoff + nk);
        *(uint4*)&p[GREG_ELEMS + sidx + 8]     = *(const uint4*)(Alo + aoff + nk + 8);
        *(uint4*)&p[2 * GREG_ELEMS + sidx]     = *(const uint4*)(Bhi + boff + nk);
        *(uint4*)&p[2 * GREG_ELEMS + sidx + 8] = *(const uint4*)(Bhi + boff + nk + 8);
        *(uint4*)&p[3 * GREG_ELEMS + sidx]     = *(const uint4*)(Blo + boff + nk);
        *(uint4*)&p[3 * GREG_ELEMS + sidx + 8] = *(const uint4*)(Blo + boff + nk + 8);
    };

    load_chunk(0, 0);
    __syncthreads();

    for (int kc = 0; kc < DM_ / 32; kc++) {
        if (kc + 1 < DM_ / 32) load_chunk(kc + 1, (kc + 1) & 1);

        const uint32_t aB = smBase + (uint32_t)(kc & 1) * (4 * GREG_B);
        const uint32_t bB = aB + 2 * GREG_B;

#pragma unroll
        for (int ks = 0; ks < 2; ks++) {
            uint32_t bh[8][2], bl[8][2];
            const int brow = wn + ((lane >> 4) & 1) * 8 + (lane & 7);
            const int bcol = ks * 16 + ((lane >> 3) & 1) * 8;
#pragma unroll
            for (int p = 0; p < 4; p++) {
                const uint32_t off = (uint32_t)((brow + p * 16) * SPAD + bcol) * 2u;
                ldsm_x4(bh[2*p][0], bh[2*p][1], bh[2*p+1][0], bh[2*p+1][1], bB + off);
                ldsm_x4(bl[2*p][0], bl[2*p][1], bl[2*p+1][0], bl[2*p+1][1],
                        bB + GREG_B + off);
            }
            const int arow = wm + (lane & 15);
            const int acol = ks * 16 + (lane >> 4) * 8;
#pragma unroll
            for (int mt = 0; mt < 2; mt++) {
                uint32_t ah[4], al[4];
                const uint32_t off = (uint32_t)((arow + mt * 16) * SPAD + acol) * 2u;
                ldsm_x4(ah[0], ah[1], ah[2], ah[3], aB + off);
                ldsm_x4(al[0], al[1], al[2], al[3], aB + GREG_B + off);
#pragma unroll
                for (int nt = 0; nt < 8; nt++) mma16816(acc[mt][nt], ah, bh[nt]);
#pragma unroll
                for (int nt = 0; nt < 8; nt++) mma16816(acc[mt][nt], ah, bl[nt]);
#pragma unroll
                for (int nt = 0; nt < 8; nt++) mma16816(acc[mt][nt], al, bh[nt]);
            }
        }
        __syncthreads();   // buffer-reuse barrier (reads of buf kc&1 done)
    }

    // ---- Epilogue ----
    const int cpair = 2 * (lane & 3);
    if (MODE == 1) {
#pragma unroll
        for (int mt = 0; mt < 2; mt++)
#pragma unroll
            for (int half = 0; half < 2; half++) {
                const int m = m0 + wm + mt * 16 + (lane >> 2) + half * 8;
                float* dst = outp + (size_t)m * DM_ + j0 + wn + cpair;
#pragma unroll
                for (int nt = 0; nt < 8; nt++)
                    *(float2*)(dst + nt * 8) =
                        make_float2(acc[mt][nt][2 * half], acc[mt][nt][2 * half + 1]);
            }
    } else {
        const int jb = j0 + wn;
        const bool isV = (jb >= 2560);
        const bool isQ = (jb < 2048);
        const int head = isQ ? (jb >> 6) : (jb < 2560 ? ((jb - 2048) >> 6) : ((jb - 2560) >> 6));
        double invf[8];
        if (!isV) {
#pragma unroll
            for (int nt = 0; nt < 8; nt++) {
                const int pi = nt * 4 + (lane & 3);
                invf[nt] = exp2(-(2.0 * pi) * (LOG2_THETA / 64.0));
            }
        }
#pragma unroll
        for (int mt = 0; mt < 2; mt++)
#pragma unroll
            for (int half = 0; half < 2; half++) {
                const int m = m0 + wm + mt * 16 + (lane >> 2) + half * 8;
                const int bb = m >> 11;
                const int t  = m & (T_ - 1);
                if (isV) {
                    const size_t doff =
                        (((size_t)bb * HKV_ + head) * T_ + t) * HD_ + cpair;
#pragma unroll
                    for (int nt = 0; nt < 8; nt++) {
                        uint32_t lo;
                        uint32_t hi = pack_hl(acc[mt][nt][2 * half],
                                              acc[mt][nt][2 * half + 1], lo);
                        *(uint32_t*)(g_Vhi + doff + nt * 8) = hi;
                        *(uint32_t*)(g_Vlo + doff + nt * 8) = lo;
                    }
                } else {
                    const int p = pos[t];
                    const float qs = isQ ? 0.125f : 1.0f;
                    const size_t doff = isQ
                        ? (((size_t)bb * HQ_  + head) * T_ + t) * HD_ + cpair
                        : (((size_t)bb * HKV_ + head) * T_ + t) * HD_ + cpair;
                    __nv_bfloat16* dsth = isQ ? g_Qhi : g_Khi;
                    __nv_bfloat16* dstl = isQ ? g_Qlo : g_Klo;
#pragma unroll
                    for (int nt = 0; nt < 8; nt++) {
                        double sn, cs;
                        sincos((double)p * invf[nt], &sn, &cs);
                        const float fc = (float)cs, fs = (float)sn;
                        const float fe = acc[mt][nt][2 * half];
                        const float fo = acc[mt][nt][2 * half + 1];
                        uint32_t lo;
                        uint32_t hi = pack_hl((fe * fc - fo * fs) * qs,
                                              (fe * fs + fo * fc) * qs, lo);
                        *(uint32_t*)(dsth + doff + nt * 8) = hi;
                        *(uint32_t*)(dstl + doff + nt * 8) = lo;
                    }
                }
            }
    }
}

// ============================================================================
// Causal GQA flash attention on tensor cores (mma.sync, split-fp32).
// R8-proven version: plain loads, single-buffered K/V, 2 barriers/iter.
// 128 threads = 4 warps; BM=128, BN=64, HD=64. 72 KB dyn smem -> 2 CTAs/SM.
// ============================================================================
#define APAD 72
#define ATTN_SMEM_BYTES ((128 * APAD * 2 + 64 * APAD * 4) * 2)

__global__ __launch_bounds__(128, 2)
void attn_mma_kernel()
{
    extern __shared__ __nv_bfloat16 smb[];
    __nv_bfloat16* Qh = smb;                   // [128][APAD]
    __nv_bfloat16* Ql = Qh + 128 * APAD;
    __nv_bfloat16* Kh = Ql + 128 * APAD;       // [64][APAD]
    __nv_bfloat16* Kl = Kh + 64 * APAD;
    __nv_bfloat16* Vh = Kl + 64 * APAD;
    __nv_bfloat16* Vl = Vh + 64 * APAD;

    const int qt = (int)gridDim.x - 1 - (int)blockIdx.x;
    const int hq = blockIdx.y;
    const int bb = blockIdx.z;
    const int hk = hq >> 2;

    const int tid = threadIdx.x;
    const int wid = tid >> 5, lane = tid & 31;
    const int wm = wid * 32;
    const int gID = lane >> 2, tig = lane & 3;

    const uint32_t QhB = smem_u32(Qh), QlB = smem_u32(Ql);
    const uint32_t KhB = smem_u32(Kh), KlB = smem_u32(Kl);
    const uint32_t VhB = smem_u32(Vh), VlB = smem_u32(Vl);

    // Load Q tile (hi/lo): one 64-elem row per thread
    {
        const size_t qoff = (((size_t)bb * HQ_ + hq) * T_ + (size_t)qt * 128 + tid) * HD_;
#pragma unroll
        for (int v = 0; v < 8; v++) {
            *(uint4*)&Qh[tid * APAD + v * 8] = *(const uint4*)(g_Qhi + qoff + v * 8);
            *(uint4*)&Ql[tid * APAD + v * 8] = *(const uint4*)(g_Qlo + qoff + v * 8);
        }
    }

    float O[2][8][4];
#pragma unroll
    for (int mt = 0; mt < 2; mt++)
#pragma unroll
        for (int nt = 0; nt < 8; nt++)
#pragma unroll
            for (int q = 0; q < 4; q++) O[mt][nt][q] = 0.f;
    float m_st[2][2], l_st[2][2];
#pragma unroll
    for (int mt = 0; mt < 2; mt++)
#pragma unroll
        for (int h2 = 0; h2 < 2; h2++) { m_st[mt][h2] = -FLT_MAX; l_st[mt][h2] = 0.f; }

    const size_t kvbase = ((size_t)bb * HKV_ + hk) * T_ * HD_;
    const int lrow = tid >> 1;
    const int lhalf = (tid & 1) * 32;
    const int ktmax = 2 * qt + 1;

    for (int kt = 0; kt <= ktmax; kt++) {
        __syncthreads();   // WAR vs previous iteration's ldsm reads
        {
            const size_t goff = kvbase + ((size_t)kt * 64 + lrow) * HD_ + lhalf;
            const int soff = lrow * APAD + lhalf;
#pragma unroll
            for (int v = 0; v < 4; v++) {
                *(uint4*)&Kh[soff + v * 8] = *(const uint4*)(g_Khi + goff + v * 8);
                *(uint4*)&Kl[soff + v * 8] = *(const uint4*)(g_Klo + goff + v * 8);
                *(uint4*)&Vh[soff + v * 8] = *(const uint4*)(g_Vhi + goff + v * 8);
                *(uint4*)&Vl[soff + v * 8] = *(const uint4*)(g_Vlo + goff + v * 8);
            }
        }
        __syncthreads();

        // ---- S = Q K^T (3 passes) ----
        float S[2][8][4];
#pragma unroll
        for (int mt = 0; mt < 2; mt++)
#pragma unroll
            for (int nt = 0; nt < 8; nt++)
#pragma unroll
                for (int q = 0; q < 4; q++) S[mt][nt][q] = 0.f;

#pragma unroll
        for (int ks = 0; ks < 4; ks++) {
            uint32_t bh[8][2], bl[8][2];
            const int brow = ((lane >> 4) & 1) * 8 + (lane & 7);
            const int bcol = ks * 16 + ((lane >> 3) & 1) * 8;
#pragma unroll
            for (int p = 0; p < 4; p++) {
                const uint32_t off = (uint32_t)((brow + p * 16) * APAD + bcol) * 2u;
                ldsm_x4(bh[2*p][0], bh[2*p][1], bh[2*p+1][0], bh[2*p+1][1], KhB + off);
                ldsm_x4(bl[2*p][0], bl[2*p][1], bl[2*p+1][0], bl[2*p+1][1], KlB + off);
            }
            const int arow = wm + (lane & 15);
            const int acol = ks * 16 + (lane >> 4) * 8;
#pragma unroll
            for (int mt = 0; mt < 2; mt++) {
                uint32_t ah[4], al[4];
                const uint32_t off = (uint32_t)((arow + mt * 16) * APAD + acol) * 2u;
                ldsm_x4(ah[0], ah[1], ah[2], ah[3], QhB + off);
                ldsm_x4(al[0], al[1], al[2], al[3], QlB + off);
#pragma unroll
                for (int nt = 0; nt < 8; nt++) mma16816(S[mt][nt], ah, bh[nt]);
#pragma unroll
                for (int nt = 0; nt < 8; nt++) mma16816(S[mt][nt], ah, bl[nt]);
#pragma unroll
                for (int nt = 0; nt < 8; nt++) mma16816(S[mt][nt], al, bh[nt]);
            }
        }

        // ---- Causal mask (diagonal tiles only) ----
        if (kt >= 2 * qt) {
            const int rg = qt * 128 + wm + gID;
            const int cg = kt * 64 + 2 * tig;
#pragma unroll
            for (int mt = 0; mt < 2; mt++)
#pragma unroll
                for (int nt = 0; nt < 8; nt++)
#pragma unroll
                    for (int h2 = 0; h2 < 2; h2++)
#pragma unroll
                        for (int e = 0; e < 2; e++)
                            if (cg + nt * 8 + e > rg + mt * 16 + h2 * 8)
                                S[mt][nt][2 * h2 + e] = -FLT_MAX;
        }

        // ---- Online softmax (quad rows; shfl_xor 1,2) ----
#pragma unroll
        for (int mt = 0; mt < 2; mt++)
#pragma unroll
            for (int h2 = 0; h2 < 2; h2++) {
                float mx = -FLT_MAX;
#pragma unroll
                for (int nt = 0; nt < 8; nt++)
                    mx = fmaxf(mx, fmaxf(S[mt][nt][2 * h2], S[mt][nt][2 * h2 + 1]));
                mx = fmaxf(mx, __shfl_xor_sync(0xffffffffu, mx, 1));
                mx = fmaxf(mx, __shfl_xor_sync(0xffffffffu, mx, 2));
                const float nm = fmaxf(m_st[mt][h2], mx);
                float sum = 0.f;
#pragma unroll
                for (int nt = 0; nt < 8; nt++) {
                    S[mt][nt][2 * h2]     = __expf(S[mt][nt][2 * h2]     - nm);
                    S[mt][nt][2 * h2 + 1] = __expf(S[mt][nt][2 * h2 + 1] - nm);
                    sum += S[mt][nt][2 * h2] + S[mt][nt][2 * h2 + 1];
                }
                sum += __shfl_xor_sync(0xffffffffu, sum, 1);
                sum += __shfl_xor_sync(0xffffffffu, sum, 2);
                const float corr = __expf(m_st[mt][h2] - nm);
                m_st[mt][h2] = nm;
                l_st[mt][h2] = l_st[mt][h2] * corr + sum;
#pragma unroll
                for (int nt = 0; nt < 8; nt++) {
                    O[mt][nt][2 * h2]     *= corr;
                    O[mt][nt][2 * h2 + 1] *= corr;
                }
            }

        // ---- O += P V (3 passes; P packed register-locally) ----
#pragma unroll
        for (int ks = 0; ks < 4; ks++) {
            uint32_t vh[8][2], vl[8][2];
            const int vrow = ks * 16 + (lane & 15);
#pragma unroll
            for (int p = 0; p < 4; p++) {
                const uint32_t off =
                    (uint32_t)(vrow * APAD + p * 16 + (lane >> 4) * 8) * 2u;
                ldsm_x4_t(vh[2*p][0], vh[2*p][1], vh[2*p+1][0], vh[2*p+1][1], VhB + off);
                ldsm_x4_t(vl[2*p][0], vl[2*p][1], vl[2*p+1][0], vl[2*p+1][1], VlB + off);
            }
#pragma unroll
            for (int mt = 0; mt < 2; mt++) {
                uint32_t ah[4], al[4];
                ah[0] = pack_hl(S[mt][2*ks][0],   S[mt][2*ks][1],   al[0]);
                ah[1] = pack_hl(S[mt][2*ks][2],   S[mt][2*ks][3],   al[1]);
                ah[2] = pack_hl(S[mt][2*ks+1][0], S[mt][2*ks+1][1], al[2]);
                ah[3] = pack_hl(S[mt][2*ks+1][2], S[mt][2*ks+1][3], al[3]);
#pragma unroll
                for (int nt = 0; nt < 8; nt++) mma16816(O[mt][nt], ah, vh[nt]);
#pragma unroll
                for (int nt = 0; nt < 8; nt++) mma16816(O[mt][nt], ah, vl[nt]);
#pragma unroll
                for (int nt = 0; nt < 8; nt++) mma16816(O[mt][nt], al, vh[nt]);
            }
        }
    }

    // ---- Finalize: /l, split hi/lo, store for out-projection ----
#pragma unroll
    for (int mt = 0; mt < 2; mt++)
#pragma unroll
        for (int h2 = 0; h2 < 2; h2++) {
            const float inv = 1.0f / l_st[mt][h2];
            const int rg = qt * 128 + wm + mt * 16 + gID + h2 * 8;
            const size_t off = ((size_t)bb * T_ + rg) * DM_ + hq * HD_ + 2 * tig;
#pragma unroll
            for (int nt = 0; nt < 8; nt++) {
                uint32_t lo;
                uint32_t hi = pack_hl(O[mt][nt][2 * h2] * inv,
                                      O[mt][nt][2 * h2 + 1] * inv, lo);
                *(uint32_t*)(g_Ohi + off + nt * 8) = hi;
                *(uint32_t*)(g_Olo + off + nt * 8) = lo;
            }
        }
}

// ============================================================================
extern "C" void kernel_launch(void* const* d_in, const int* in_sizes, int n_in,
                              void* d_out, int out_size)
{
    const float* x   = (const float*)d_in[0];
    const int*   pos = (const int*)  d_in[1];
    const float* WQ  = (const float*)d_in[2];
    const float* WK  = (const float*)d_in[3];
    const float* WV  = (const float*)d_in[4];
    const float* WO  = (const float*)d_in[5];
    float* out = (float*)d_out;

    cudaFuncSetAttribute(gemm_mma_kernel<0>, cudaFuncAttributeMaxDynamicSharedMemorySize,
                         GEMM_SMEM_BYTES);
    cudaFuncSetAttribute(gemm_mma_kernel<1>, cudaFuncAttributeMaxDynamicSharedMemorySize,
                         GEMM_SMEM_BYTES);
    cudaFuncSetAttribute(attn_mma_kernel, cudaFuncAttributeMaxDynamicSharedMemorySize,
                         ATTN_SMEM_BYTES);

    // 0) hi/lo bf16 conversion of x and all weights
    cvt_kernel<<<CVT_TOTAL_F4 / 256, 256>>>(x, WQ, WK, WV, WO);

    // 1) QKV projection + RoPE (tensor cores) -> bf16 hi/lo Q/K/V
    gemm_mma_kernel<0><<<dim3(24, (B_ * T_) / 128), 256, GEMM_SMEM_BYTES>>>(pos, nullptr);

    // 2) Flash attention (tensor cores, split-fp32) -> bf16 hi/lo O
    attn_mma_kernel<<<dim3(T_ / 128, HQ_, B_), 128, ATTN_SMEM_BYTES>>>();

    // 3) Output projection (tensor cores) -> fp32 out
    gemm_mma_kernel<1><<<dim3(16, (B_ * T_) / 128), 256, GEMM_SMEM_BYTES>>>(pos, out);
}